// round 16
// baseline (speedup 1.0000x reference)
#include <cuda_runtime.h>
#include <cuda_bf16.h>
#include <cstdint>
#include <math.h>

#define N_TOK 8192
#define C_DIM 1024
#define E_NUM 8
#define DFF_DIM 4096
#define HROWS (2 * N_TOK + 128)

// double-buffered smem layout (words): round-13 proven conflict-free pitches
#define AW 2048
#define BW 2560
#define OFF_AL 4096
#define OFF_BH 8192
#define OFF_BL 13312
#define SMEM_DYN_BYTES ((OFF_BL + 2 * BW) * 4)   // 73728 B

#define NTHREADS 384   // 8 compute warps + 4 producer warps
#define NB_SYNC(id)   asm volatile("bar.sync %0, 384;"   :: "r"(id) : "memory")
#define NB_ARRIVE(id) asm volatile("bar.arrive %0, 384;" :: "r"(id) : "memory")
// barrier ids: F0=1 F1=2 (filled), C0=3 C1=4 (consumed)

// ---------------- scratch (~270MB total — proven-passing level) ---------------
__device__ float g_h[HROWS * DFF_DIM];     // fp32 gelu(x@w1) rows, bucketed
__device__ int   g_counts[E_NUM];
__device__ int   g_offsets[E_NUM];
__device__ int   g_tok[E_NUM * N_TOK];
__device__ float g_wgt[E_NUM * N_TOK];

// ---------------- helpers -----------------------------------------------------
__device__ __forceinline__ void mma_bf16(float* d, const uint32_t* a, const uint32_t* b) {
    asm volatile(
        "mma.sync.aligned.m16n8k16.row.col.f32.bf16.bf16.f32 "
        "{%0,%1,%2,%3}, {%4,%5,%6,%7}, {%8,%9}, {%0,%1,%2,%3};"
        : "+f"(d[0]), "+f"(d[1]), "+f"(d[2]), "+f"(d[3])
        : "r"(a[0]), "r"(a[1]), "r"(a[2]), "r"(a[3]), "r"(b[0]), "r"(b[1]));
}

// truncation split of a pair: hi = top 16 bits (exact trunc), lo = exact residual
__device__ __forceinline__ void tsplit2(float vx, float vy, uint32_t& hi, uint32_t& lo) {
    uint32_t ax = __float_as_uint(vx), ay = __float_as_uint(vy);
    float lx = vx - __uint_as_float(ax & 0xFFFF0000u);
    float ly = vy - __uint_as_float(ay & 0xFFFF0000u);
    hi = __byte_perm(ax, ay, 0x7632);
    lo = __byte_perm(__float_as_uint(lx), __float_as_uint(ly), 0x7632);
}

__device__ __forceinline__ float gelu_exact(float v) {
    return 0.5f * v * (1.0f + erff(v * 0.70710678118654752f));
}

// ---------------- small kernels (verbatim) -------------------------------------
__global__ void zero_counts_kernel() {
    if (threadIdx.x < E_NUM) g_counts[threadIdx.x] = 0;
}
__global__ void zero_out_kernel(float* out, int n) {
    for (int i = blockIdx.x * blockDim.x + threadIdx.x; i < n; i += gridDim.x * blockDim.x)
        out[i] = 0.0f;
}
__global__ void offsets_kernel() {
    int run = 0;
    for (int e = 0; e < E_NUM; e++) { g_offsets[e] = run; run += g_counts[e]; }
}

__global__ void router_kernel(const float* __restrict__ x,
                              const float* __restrict__ rw,
                              const float* __restrict__ rb) {
    int t = blockIdx.x;
    int tid = threadIdx.x;
    __shared__ float red[128][E_NUM];
    float acc[E_NUM];
#pragma unroll
    for (int e = 0; e < E_NUM; e++) acc[e] = 0.0f;
    const float* xr = x + (size_t)t * C_DIM;
    for (int c = tid; c < C_DIM; c += 128) {
        float xv = xr[c];
        const float* w = &rw[c * E_NUM];
#pragma unroll
        for (int e = 0; e < E_NUM; e++) acc[e] += xv * w[e];
    }
#pragma unroll
    for (int e = 0; e < E_NUM; e++) red[tid][e] = acc[e];
    __syncthreads();
    for (int s = 64; s > 0; s >>= 1) {
        if (tid < s) {
#pragma unroll
            for (int e = 0; e < E_NUM; e++) red[tid][e] += red[tid + s][e];
        }
        __syncthreads();
    }
    if (tid == 0) {
        float lg[E_NUM], p[E_NUM];
        float mx = -1e30f;
#pragma unroll
        for (int e = 0; e < E_NUM; e++) { lg[e] = red[0][e] + rb[e]; mx = fmaxf(mx, lg[e]); }
        float sum = 0.0f;
#pragma unroll
        for (int e = 0; e < E_NUM; e++) { p[e] = expf(lg[e] - mx); sum += p[e]; }
        float inv = 1.0f / sum;
#pragma unroll
        for (int e = 0; e < E_NUM; e++) p[e] *= inv;
        int i1 = 0;
#pragma unroll
        for (int e = 1; e < E_NUM; e++) if (p[e] > p[i1]) i1 = e;
        int i2 = (i1 == 0) ? 1 : 0;
#pragma unroll
        for (int e = 0; e < E_NUM; e++) if (e != i1 && p[e] > p[i2]) i2 = e;
        int s1 = atomicAdd(&g_counts[i1], 1);
        g_tok[i1 * N_TOK + s1] = t;  g_wgt[i1 * N_TOK + s1] = p[i1];
        int s2 = atomicAdd(&g_counts[i2], 1);
        g_tok[i2 * N_TOK + s2] = t;  g_wgt[i2 * N_TOK + s2] = p[i2];
    }
}

// ---------------- warp-specialized HMMA GEMM -----------------------------------
// CTA 128m x 128n, stage k=32. wid 0-7: compute (2m x 4n, warp tile 64x32,
// round-10 fragment math verbatim). wid 8-11: producers (one per SMSP) doing
// all LDG -> tsplit -> STS into round-13 double-buffered layout.
// Handoff: producers arrive F[b] after fill / sync C[b] before refill;
// consumers sync F[b] before compute / arrive C[b] after compute.
template <int KTOT, int NDIM, bool G1>
__global__ void __launch_bounds__(NTHREADS, 1)
gemm_hmma(const float* __restrict__ A_g, const float* __restrict__ B_g,
          const float* __restrict__ bias_g, float* __restrict__ out) {
    extern __shared__ __align__(16) uint32_t sdyn[];
    __shared__ int   srow_s[128];
    __shared__ int   stok_s[128];
    __shared__ float swgt_s[128];

    int e = blockIdx.z;
    int cnt = g_counts[e];
    int m0 = blockIdx.y * 128;
    if (m0 >= cnt) return;
    int n0 = blockIdx.x * 128;
    int off = g_offsets[e];

    int tid = threadIdx.x, lane = tid & 31, wid = tid >> 5;

    if (tid < 128) {
        int m = m0 + tid;
        int sr = 0, tk = 0; float wg = 0.0f;
        if (m < cnt) {
            tk = g_tok[e * N_TOK + m];
            wg = g_wgt[e * N_TOK + m];
            sr = G1 ? tk : (off + m);
        }
        srow_s[tid] = sr; stok_s[tid] = tk; swgt_s[tid] = wg;
    }
    __syncthreads();

    const float* Abase = G1 ? A_g : g_h;
    const float* Bp = B_g + (size_t)e * KTOT * NDIM + n0;
    const int NS = KTOT / 32;

    if (wid >= 8) {
        // ================= PRODUCER (128 threads) =================
        int p = tid - 256;                 // 0..127
        int prA = p & 15;                  // k-pair within stage
        int rb  = p >> 4;                  // 0..7  (rows rb + 8i)
        int slA = prA >> 3, wA = prA & 7;
        int posA = (wA & 3) * 2 + (wA >> 2);
        const float* bcol = Bp + p;        // B column n0+p
        int bws0 = p * 10;

        for (int t = 0; t < NS; t++) {
            if (t >= 2) NB_SYNC(3 + (t & 1));          // wait consumed
            int b = t & 1;
            uint32_t* dAh = sdyn + b * AW;
            uint32_t* dAl = sdyn + OFF_AL + b * AW;
            uint32_t* dBh = sdyn + OFF_BH + b * BW;
            uint32_t* dBl = sdyn + OFF_BL + b * BW;
            int ka = t * 32;
#pragma unroll 4
            for (int i = 0; i < 16; i++) {
                int r = rb + 8 * i;
                const float* ap = Abase + (size_t)srow_s[r] * KTOT + 2 * prA + ka;
                float2 v = *(const float2*)ap;
                uint32_t hi, lo;
                tsplit2(v.x, v.y, hi, lo);
                int aw = (slA * 128 + r) * 8 + posA;
                dAh[aw] = hi;
                dAl[aw] = lo;
            }
#pragma unroll 4
            for (int i = 0; i < 16; i++) {
                const float* bp = bcol + (size_t)(ka + 2 * i) * NDIM;
                float bx = bp[0];
                float by = bp[NDIM];
                uint32_t hi, lo;
                tsplit2(bx, by, hi, lo);
                int slB = i >> 3, wB = i & 7;
                int posB = (wB & 3) * 2 + (wB >> 2);
                dBh[slB * 1280 + bws0 + posB] = hi;
                dBl[slB * 1280 + bws0 + posB] = lo;
            }
            NB_ARRIVE(1 + b);                          // filled
        }
        // balance consumers' last two C arrivals
        NB_SYNC(3 + (NS & 1));
        NB_SYNC(3 + ((NS + 1) & 1));
        return;
    }

    // ================= CONSUMER (256 threads, 8 warps) =================
    int wm = wid >> 2, wn = wid & 3;
    int l4 = lane >> 2, lc = lane & 3;
    const float* bias = bias_g + (size_t)e * NDIM + n0;

    float acc[4][4][4];
#pragma unroll
    for (int a = 0; a < 4; a++)
#pragma unroll
        for (int b = 0; b < 4; b++)
#pragma unroll
            for (int c = 0; c < 4; c++) acc[a][b][c] = 0.0f;

    for (int s = 0; s < NS; s++) {
        int b = s & 1;
        NB_SYNC(1 + b);                                // wait filled
        const uint32_t* cAh = sdyn + b * AW;
        const uint32_t* cAl = sdyn + OFF_AL + b * AW;
        const uint32_t* cBh = sdyn + OFF_BH + b * BW;
        const uint32_t* cBl = sdyn + OFF_BL + b * BW;
#pragma unroll
        for (int ks = 0; ks < 2; ks++) {
            uint32_t bhf[4][2], blf[4][2];
#pragma unroll
            for (int nt = 0; nt < 4; nt++) {
                int n = wn * 32 + nt * 8 + l4;
                int wbi = (ks * 128 + n) * 10 + 2 * lc;
                uint2 h = *(const uint2*)&cBh[wbi];
                uint2 l = *(const uint2*)&cBl[wbi];
                bhf[nt][0] = h.x; bhf[nt][1] = h.y;
                blf[nt][0] = l.x; blf[nt][1] = l.y;
            }
            uint32_t ahf[4][4], alf[4][4];
#pragma unroll
            for (int mt = 0; mt < 4; mt++) {
                int r = wm * 64 + mt * 16 + l4;
                int wa0 = (ks * 128 + r) * 8 + 2 * lc;
                int wa1 = (ks * 128 + r + 8) * 8 + 2 * lc;
                uint2 h0 = *(const uint2*)&cAh[wa0];
                uint2 h1 = *(const uint2*)&cAh[wa1];
                uint2 l0 = *(const uint2*)&cAl[wa0];
                uint2 l1 = *(const uint2*)&cAl[wa1];
                ahf[mt][0] = h0.x; ahf[mt][1] = h1.x; ahf[mt][2] = h0.y; ahf[mt][3] = h1.y;
                alf[mt][0] = l0.x; alf[mt][1] = l1.x; alf[mt][2] = l0.y; alf[mt][3] = l1.y;
            }
#pragma unroll
            for (int mt = 0; mt < 4; mt++)
#pragma unroll
                for (int nt = 0; nt < 4; nt++)
                    mma_bf16(acc[mt][nt], ahf[mt], bhf[nt]);
#pragma unroll
            for (int mt = 0; mt < 4; mt++)
#pragma unroll
                for (int nt = 0; nt < 4; nt++)
                    mma_bf16(acc[mt][nt], ahf[mt], blf[nt]);
#pragma unroll
            for (int mt = 0; mt < 4; mt++)
#pragma unroll
                for (int nt = 0; nt < 4; nt++)
                    mma_bf16(acc[mt][nt], alf[mt], bhf[nt]);
        }
        NB_ARRIVE(3 + b);                              // consumed
    }

    // ---- epilogue (round-10 verbatim) ----
#pragma unroll
    for (int mt = 0; mt < 4; mt++) {
#pragma unroll
        for (int half = 0; half < 2; half++) {
            int mrow = wm * 64 + mt * 16 + l4 + half * 8;
            if (m0 + mrow >= cnt) continue;
            if (G1) {
                float* hrow = g_h + (size_t)(off + m0 + mrow) * DFF_DIM + n0;
#pragma unroll
                for (int nt = 0; nt < 4; nt++) {
                    int c = wn * 32 + nt * 8 + lc * 2;
                    float v0 = gelu_exact(acc[mt][nt][half * 2 + 0] + bias[c]);
                    float v1 = gelu_exact(acc[mt][nt][half * 2 + 1] + bias[c + 1]);
                    *(float2*)(hrow + c) = make_float2(v0, v1);
                }
            } else {
                int tok = stok_s[mrow];
                float wgt = swgt_s[mrow];
                float* orow = out + (size_t)tok * C_DIM + n0;
#pragma unroll
                for (int nt = 0; nt < 4; nt++) {
                    int c = wn * 32 + nt * 8 + lc * 2;
                    atomicAdd(orow + c,     wgt * (acc[mt][nt][half * 2 + 0] + bias[c]));
                    atomicAdd(orow + c + 1, wgt * (acc[mt][nt][half * 2 + 1] + bias[c + 1]));
                }
            }
        }
    }
}

// ---------------- launch ------------------------------------------------------
extern "C" void kernel_launch(void* const* d_in, const int* in_sizes, int n_in,
                              void* d_out, int out_size) {
    const float* x  = (const float*)d_in[0];
    const float* rw = (const float*)d_in[1];
    const float* rb = (const float*)d_in[2];
    const float* w1 = (const float*)d_in[3];
    const float* b1 = (const float*)d_in[4];
    const float* w2 = (const float*)d_in[5];
    const float* b2 = (const float*)d_in[6];
    float* out = (float*)d_out;

    cudaFuncSetAttribute(gemm_hmma<C_DIM, DFF_DIM, true>,
                         cudaFuncAttributeMaxDynamicSharedMemorySize, SMEM_DYN_BYTES);
    cudaFuncSetAttribute(gemm_hmma<DFF_DIM, C_DIM, false>,
                         cudaFuncAttributeMaxDynamicSharedMemorySize, SMEM_DYN_BYTES);

    // gemm1 is the 4th launch (ncu -s 5 -c 1 profiles it)
    zero_counts_kernel<<<1, 32>>>();
    router_kernel<<<N_TOK, 128>>>(x, rw, rb);
    offsets_kernel<<<1, 1>>>();
    {
        dim3 g(DFF_DIM / 128, N_TOK / 128, E_NUM);
        gemm_hmma<C_DIM, DFF_DIM, true><<<g, NTHREADS, SMEM_DYN_BYTES>>>(x, w1, b1, nullptr);
    }
    zero_out_kernel<<<512, 256>>>(out, N_TOK * C_DIM);
    {
        dim3 g(C_DIM / 128, N_TOK / 128, E_NUM);
        gemm_hmma<DFF_DIM, C_DIM, false><<<g, NTHREADS, SMEM_DYN_BYTES>>>(nullptr, w2, b2, out);
    }
}

// round 17
// speedup vs baseline: 4.5746x; 4.5746x over previous
#include <cuda_runtime.h>
#include <cuda_bf16.h>
#include <cstdint>
#include <math.h>

#define N_TOK 8192
#define C_DIM 1024
#define E_NUM 8
#define DFF_DIM 4096
#define HROWS (2 * N_TOK + 128)

// ---------------- scratch (~270MB total — proven-passing level) ---------------
__device__ float g_h[HROWS * DFF_DIM];     // fp32 gelu(x@w1) rows, bucketed
__device__ int   g_counts[E_NUM];
__device__ int   g_offsets[E_NUM];
__device__ int   g_tok[E_NUM * N_TOK];
__device__ float g_wgt[E_NUM * N_TOK];

// ---------------- helpers -----------------------------------------------------
__device__ __forceinline__ void mma_bf16(float* d, const uint32_t* a, const uint32_t* b) {
    asm volatile(
        "mma.sync.aligned.m16n8k16.row.col.f32.bf16.bf16.f32 "
        "{%0,%1,%2,%3}, {%4,%5,%6,%7}, {%8,%9}, {%0,%1,%2,%3};"
        : "+f"(d[0]), "+f"(d[1]), "+f"(d[2]), "+f"(d[3])
        : "r"(a[0]), "r"(a[1]), "r"(a[2]), "r"(a[3]), "r"(b[0]), "r"(b[1]));
}

// truncation split of a pair: hi = top 16 bits (exact trunc), lo = exact residual
__device__ __forceinline__ void tsplit2(float vx, float vy, uint32_t& hi, uint32_t& lo) {
    uint32_t ax = __float_as_uint(vx), ay = __float_as_uint(vy);
    float lx = vx - __uint_as_float(ax & 0xFFFF0000u);
    float ly = vy - __uint_as_float(ay & 0xFFFF0000u);
    hi = __byte_perm(ax, ay, 0x7632);
    lo = __byte_perm(__float_as_uint(lx), __float_as_uint(ly), 0x7632);
}

__device__ __forceinline__ float gelu_exact(float v) {
    return 0.5f * v * (1.0f + erff(v * 0.70710678118654752f));
}

// ---------------- small kernels (verbatim) -------------------------------------
__global__ void zero_counts_kernel() {
    if (threadIdx.x < E_NUM) g_counts[threadIdx.x] = 0;
}
__global__ void zero_out_kernel(float* out, int n) {
    for (int i = blockIdx.x * blockDim.x + threadIdx.x; i < n; i += gridDim.x * blockDim.x)
        out[i] = 0.0f;
}
__global__ void offsets_kernel() {
    int run = 0;
    for (int e = 0; e < E_NUM; e++) { g_offsets[e] = run; run += g_counts[e]; }
}

__global__ void router_kernel(const float* __restrict__ x,
                              const float* __restrict__ rw,
                              const float* __restrict__ rb) {
    int t = blockIdx.x;
    int tid = threadIdx.x;
    __shared__ float red[128][E_NUM];
    float acc[E_NUM];
#pragma unroll
    for (int e = 0; e < E_NUM; e++) acc[e] = 0.0f;
    const float* xr = x + (size_t)t * C_DIM;
    for (int c = tid; c < C_DIM; c += 128) {
        float xv = xr[c];
        const float* w = &rw[c * E_NUM];
#pragma unroll
        for (int e = 0; e < E_NUM; e++) acc[e] += xv * w[e];
    }
#pragma unroll
    for (int e = 0; e < E_NUM; e++) red[tid][e] = acc[e];
    __syncthreads();
    for (int s = 64; s > 0; s >>= 1) {
        if (tid < s) {
#pragma unroll
            for (int e = 0; e < E_NUM; e++) red[tid][e] += red[tid + s][e];
        }
        __syncthreads();
    }
    if (tid == 0) {
        float lg[E_NUM], p[E_NUM];
        float mx = -1e30f;
#pragma unroll
        for (int e = 0; e < E_NUM; e++) { lg[e] = red[0][e] + rb[e]; mx = fmaxf(mx, lg[e]); }
        float sum = 0.0f;
#pragma unroll
        for (int e = 0; e < E_NUM; e++) { p[e] = expf(lg[e] - mx); sum += p[e]; }
        float inv = 1.0f / sum;
#pragma unroll
        for (int e = 0; e < E_NUM; e++) p[e] *= inv;
        int i1 = 0;
#pragma unroll
        for (int e = 1; e < E_NUM; e++) if (p[e] > p[i1]) i1 = e;
        int i2 = (i1 == 0) ? 1 : 0;
#pragma unroll
        for (int e = 0; e < E_NUM; e++) if (e != i1 && p[e] > p[i2]) i2 = e;
        int s1 = atomicAdd(&g_counts[i1], 1);
        g_tok[i1 * N_TOK + s1] = t;  g_wgt[i1 * N_TOK + s1] = p[i1];
        int s2 = atomicAdd(&g_counts[i2], 1);
        g_tok[i2 * N_TOK + s2] = t;  g_wgt[i2 * N_TOK + s2] = p[i2];
    }
}

// ---------------- HMMA GEMM (round-10 structure, vectorized staging) ----------
// CTA 128m x 128n, stage k=32 (2 k16 slices). 8 warps (2m x 4n), warp tile 64x32.
// A smem: [slice][row][8 words] pitch 8; B smem: [slice][n][8 words] pitch 10.
// word for k-pair w stored at pos(w) = (w&3)*2 + (w>>2) (fragment LDS.64-friendly).
// Staging (vectorized): A thread = (k-quad qA, rows (t>>3)+32i) via LDG.128;
// B thread = (4 adjacent cols, k-pair (t>>5)+8i) via 2x LDG.128 per unit.
template <int KTOT, int NDIM, bool G1>
__global__ void __launch_bounds__(256, 1)
gemm_hmma(const float* __restrict__ A_g, const float* __restrict__ B_g,
          const float* __restrict__ bias_g, float* __restrict__ out) {
    __shared__ __align__(16) uint32_t sAh[2 * 128 * 8];
    __shared__ __align__(16) uint32_t sAl[2 * 128 * 8];
    __shared__ __align__(16) uint32_t sBh[2 * 128 * 10];
    __shared__ __align__(16) uint32_t sBl[2 * 128 * 10];
    __shared__ int   srow_s[128];
    __shared__ int   stok_s[128];
    __shared__ float swgt_s[128];

    int e = blockIdx.z;
    int cnt = g_counts[e];
    int m0 = blockIdx.y * 128;
    if (m0 >= cnt) return;
    int n0 = blockIdx.x * 128;
    int off = g_offsets[e];

    int tid = threadIdx.x, lane = tid & 31, wid = tid >> 5;
    int wm = wid >> 2, wn = wid & 3;
    int l4 = lane >> 2, lc = lane & 3;

    if (tid < 128) {
        int m = m0 + tid;
        int sr = 0, tk = 0; float wg = 0.0f;
        if (m < cnt) {
            tk = g_tok[e * N_TOK + m];
            wg = g_wgt[e * N_TOK + m];
            sr = G1 ? tk : (off + m);
        }
        srow_s[tid] = sr; stok_s[tid] = tk; swgt_s[tid] = wg;
    }
    __syncthreads();

    const float* Abase = G1 ? A_g : g_h;
    const float* Bp = B_g + (size_t)e * KTOT * NDIM + n0;
    const float* bias = bias_g + (size_t)e * NDIM + n0;

    // ---- A staging: qA = t&7 (k = 4*qA..4*qA+3), rows r = (t>>3) + 32*i ----
    int qA = tid & 7;
    int slA = qA >> 2;                         // slice of both pairs in this quad
    int w0 = (2 * qA) & 7, w1 = w0 + 1;
    int posA0 = (w0 & 3) * 2 + (w0 >> 2);
    int posA1 = (w1 & 3) * 2 + (w1 >> 2);
    const float* aptr[4];
    int awb[4];
#pragma unroll
    for (int i = 0; i < 4; i++) {
        int r = (tid >> 3) + 32 * i;
        aptr[i] = Abase + (size_t)srow_s[r] * KTOT + 4 * qA;
        awb[i] = (slA * 128 + r) * 8;
    }
    // ---- B staging: colgroup g = t&31 (cols 4g..4g+3), kp = (t>>5) + 8*i ----
    int cg = tid & 31;
    int kpb = tid >> 5;                        // 0..7 ; slice = i, w = kpb
    int posB = ((kpb & 3) * 2) + (kpb >> 2);
    const float* bptr[2];
    int bwb[2];
#pragma unroll
    for (int i = 0; i < 2; i++) {
        int kp = kpb + 8 * i;
        bptr[i] = Bp + (size_t)(2 * kp) * NDIM + 4 * cg;
        bwb[i] = i * 1280 + (4 * cg) * 10 + posB;   // +10 per column
    }

    float acc[4][4][4];
#pragma unroll
    for (int a = 0; a < 4; a++)
#pragma unroll
        for (int b = 0; b < 4; b++)
#pragma unroll
            for (int c = 0; c < 4; c++) acc[a][b][c] = 0.0f;

    const int NS = KTOT / 32;
    float4 pa[4];
    float4 pb0[2], pb1[2];
#pragma unroll
    for (int i = 0; i < 4; i++) pa[i] = *(const float4*)(aptr[i]);
#pragma unroll
    for (int i = 0; i < 2; i++) {
        pb0[i] = *(const float4*)(bptr[i]);
        pb1[i] = *(const float4*)(bptr[i] + NDIM);
    }

    for (int s = 0; s < NS; s++) {
        // store prefetched chunk into smem
#pragma unroll
        for (int i = 0; i < 4; i++) {
            uint32_t h0, l0, h1, l1;
            tsplit2(pa[i].x, pa[i].y, h0, l0);
            tsplit2(pa[i].z, pa[i].w, h1, l1);
            sAh[awb[i] + posA0] = h0;  sAl[awb[i] + posA0] = l0;
            sAh[awb[i] + posA1] = h1;  sAl[awb[i] + posA1] = l1;
        }
#pragma unroll
        for (int i = 0; i < 2; i++) {
            uint32_t h, l;
            tsplit2(pb0[i].x, pb1[i].x, h, l);
            sBh[bwb[i]]      = h;  sBl[bwb[i]]      = l;
            tsplit2(pb0[i].y, pb1[i].y, h, l);
            sBh[bwb[i] + 10] = h;  sBl[bwb[i] + 10] = l;
            tsplit2(pb0[i].z, pb1[i].z, h, l);
            sBh[bwb[i] + 20] = h;  sBl[bwb[i] + 20] = l;
            tsplit2(pb0[i].w, pb1[i].w, h, l);
            sBh[bwb[i] + 30] = h;  sBl[bwb[i] + 30] = l;
        }
        __syncthreads();
        if (s + 1 < NS) {   // prefetch next stage (overlaps compute)
            size_t ka = (size_t)(s + 1) * 32;
#pragma unroll
            for (int i = 0; i < 4; i++) pa[i] = *(const float4*)(aptr[i] + ka);
            size_t kb = ka * NDIM;
#pragma unroll
            for (int i = 0; i < 2; i++) {
                pb0[i] = *(const float4*)(bptr[i] + kb);
                pb1[i] = *(const float4*)(bptr[i] + kb + NDIM);
            }
        }

#pragma unroll
        for (int ks = 0; ks < 2; ks++) {
            uint32_t bhf[4][2], blf[4][2];
#pragma unroll
            for (int nt = 0; nt < 4; nt++) {
                int n = wn * 32 + nt * 8 + l4;
                int wbi = (ks * 128 + n) * 10 + 2 * lc;
                uint2 h = *(const uint2*)&sBh[wbi];
                uint2 l = *(const uint2*)&sBl[wbi];
                bhf[nt][0] = h.x; bhf[nt][1] = h.y;
                blf[nt][0] = l.x; blf[nt][1] = l.y;
            }
            uint32_t ahf[4][4], alf[4][4];
#pragma unroll
            for (int mt = 0; mt < 4; mt++) {
                int r = wm * 64 + mt * 16 + l4;
                int wa0 = (ks * 128 + r) * 8 + 2 * lc;
                int wa1 = (ks * 128 + r + 8) * 8 + 2 * lc;
                uint2 h0 = *(const uint2*)&sAh[wa0];
                uint2 h1 = *(const uint2*)&sAh[wa1];
                uint2 l0 = *(const uint2*)&sAl[wa0];
                uint2 l1 = *(const uint2*)&sAl[wa1];
                ahf[mt][0] = h0.x; ahf[mt][1] = h1.x; ahf[mt][2] = h0.y; ahf[mt][3] = h1.y;
                alf[mt][0] = l0.x; alf[mt][1] = l1.x; alf[mt][2] = l0.y; alf[mt][3] = l1.y;
            }
#pragma unroll
            for (int mt = 0; mt < 4; mt++)
#pragma unroll
                for (int nt = 0; nt < 4; nt++)
                    mma_bf16(acc[mt][nt], ahf[mt], bhf[nt]);
#pragma unroll
            for (int mt = 0; mt < 4; mt++)
#pragma unroll
                for (int nt = 0; nt < 4; nt++)
                    mma_bf16(acc[mt][nt], ahf[mt], blf[nt]);
#pragma unroll
            for (int mt = 0; mt < 4; mt++)
#pragma unroll
                for (int nt = 0; nt < 4; nt++)
                    mma_bf16(acc[mt][nt], alf[mt], bhf[nt]);
        }
        __syncthreads();
    }

    // ---- epilogue (round-10 verbatim) ----
#pragma unroll
    for (int mt = 0; mt < 4; mt++) {
#pragma unroll
        for (int half = 0; half < 2; half++) {
            int mrow = wm * 64 + mt * 16 + l4 + half * 8;
            if (m0 + mrow >= cnt) continue;
            if (G1) {
                float* hrow = g_h + (size_t)(off + m0 + mrow) * DFF_DIM + n0;
#pragma unroll
                for (int nt = 0; nt < 4; nt++) {
                    int c = wn * 32 + nt * 8 + lc * 2;
                    float v0 = gelu_exact(acc[mt][nt][half * 2 + 0] + bias[c]);
                    float v1 = gelu_exact(acc[mt][nt][half * 2 + 1] + bias[c + 1]);
                    *(float2*)(hrow + c) = make_float2(v0, v1);
                }
            } else {
                int tok = stok_s[mrow];
                float wgt = swgt_s[mrow];
                float* orow = out + (size_t)tok * C_DIM + n0;
#pragma unroll
                for (int nt = 0; nt < 4; nt++) {
                    int c = wn * 32 + nt * 8 + lc * 2;
                    atomicAdd(orow + c,     wgt * (acc[mt][nt][half * 2 + 0] + bias[c]));
                    atomicAdd(orow + c + 1, wgt * (acc[mt][nt][half * 2 + 1] + bias[c + 1]));
                }
            }
        }
    }
}

// ---------------- launch ------------------------------------------------------
extern "C" void kernel_launch(void* const* d_in, const int* in_sizes, int n_in,
                              void* d_out, int out_size) {
    const float* x  = (const float*)d_in[0];
    const float* rw = (const float*)d_in[1];
    const float* rb = (const float*)d_in[2];
    const float* w1 = (const float*)d_in[3];
    const float* b1 = (const float*)d_in[4];
    const float* w2 = (const float*)d_in[5];
    const float* b2 = (const float*)d_in[6];
    float* out = (float*)d_out;

    // gemm1 is the 4th launch (ncu -s 5 -c 1 profiles it);
    // zero_out precedes gemm2 in stream order.
    zero_counts_kernel<<<1, 32>>>();
    router_kernel<<<N_TOK, 128>>>(x, rw, rb);
    offsets_kernel<<<1, 1>>>();
    {
        dim3 g(DFF_DIM / 128, N_TOK / 128, E_NUM);
        gemm_hmma<C_DIM, DFF_DIM, true><<<g, 256>>>(x, w1, b1, nullptr);
    }
    zero_out_kernel<<<512, 256>>>(out, N_TOK * C_DIM);
    {
        dim3 g(C_DIM / 128, N_TOK / 128, E_NUM);
        gemm_hmma<DFF_DIM, C_DIM, false><<<g, 256>>>(nullptr, w2, b2, out);
    }
}